// round 6
// baseline (speedup 1.0000x reference)
#include <cuda_runtime.h>
#include <cuda_fp16.h>
#include <stdint.h>
#include <math.h>

// ---------------- problem constants ----------------
#define Bsz   8
#define Tlen  4096
#define Cdim  512
#define Hdim  512
#define Mtot  (Bsz * Tlen)          // 32768 rows
#define NCH   32
#define CHUNK (Tlen / NCH)

// ---------------- GEMM tiling ----------------
#define BM     128
#define BN     128
#define BK     32                   // fp16 K per stage
#define STAGES 4
#define NIT    64                   // 2 terms * (1024/32)
#define AROWB  80                   // padded smem row stride (bytes)
#define ASTG   (BM * AROWB)         // 10240
#define BSTG   (BN * AROWB)         // 10240
#define STG    (ASTG + BSTG)        // 20480
#define SMEMT  (STAGES * STG)       // 81920

// ---------------- device scratch ----------------
__device__ float g_z[(size_t)Mtot * Hdim];
__device__ float g_f[(size_t)Mtot * Hdim];
__device__ float g_o[(size_t)Mtot * Hdim];
__device__ float g_P[Bsz * NCH * Hdim];
__device__ float g_L[Bsz * NCH * Hdim];
__device__ float g_hin[Bsz * NCH * Hdim];
__device__ __half g_xhi[(size_t)Mtot * Cdim];
__device__ __half g_xlo[(size_t)Mtot * Cdim];
__device__ __half g_wt[3][(size_t)Hdim * 2 * Cdim];   // [gate][h*1024 + kk], fp16

// ---------------- PTX helpers ----------------
__device__ __forceinline__ uint32_t smem_u32(const void* p) {
    uint32_t a;
    asm("{ .reg .u64 t; cvta.to.shared.u64 t, %1; cvt.u32.u64 %0, t; }" : "=r"(a) : "l"(p));
    return a;
}
__device__ __forceinline__ void cpa16(uint32_t dst, const void* src, uint32_t sz) {
    asm volatile("cp.async.cg.shared.global [%0], [%1], 16, %2;"
                 :: "r"(dst), "l"(src), "r"(sz) : "memory");
}
#define CP_COMMIT() asm volatile("cp.async.commit_group;" ::: "memory")
#define CP_WAIT2()  asm volatile("cp.async.wait_group 2;" ::: "memory")

#define LDSM4(r, a) \
    asm volatile("ldmatrix.sync.aligned.m8n8.x4.shared.b16 {%0,%1,%2,%3}, [%4];" \
        : "=r"((r)[0]), "=r"((r)[1]), "=r"((r)[2]), "=r"((r)[3]) : "r"(a))

__device__ __forceinline__ void mma16816(float* c, const uint32_t* a,
                                         uint32_t b0, uint32_t b1) {
    asm volatile(
        "mma.sync.aligned.m16n8k16.row.col.f32.f16.f16.f32 "
        "{%0,%1,%2,%3}, {%4,%5,%6,%7}, {%8,%9}, {%0,%1,%2,%3};"
        : "+f"(c[0]), "+f"(c[1]), "+f"(c[2]), "+f"(c[3])
        : "r"(a[0]), "r"(a[1]), "r"(a[2]), "r"(a[3]), "r"(b0), "r"(b1));
}

// ---------------- prep kernels ----------------
__global__ __launch_bounds__(256) void prep_x(const float* __restrict__ x) {
    size_t i = (size_t)blockIdx.x * 256 + threadIdx.x;   // over Mtot*Cdim/4
    float4 v = ((const float4*)x)[i];
    __half h0 = __float2half(v.x), h1 = __float2half(v.y);
    __half h2 = __float2half(v.z), h3 = __float2half(v.w);
    __half l0 = __float2half(v.x - __half2float(h0));
    __half l1 = __float2half(v.y - __half2float(h1));
    __half l2 = __float2half(v.z - __half2float(h2));
    __half l3 = __float2half(v.w - __half2float(h3));
    __half2* hp = (__half2*)g_xhi;
    __half2* lp = (__half2*)g_xlo;
    hp[i*2]   = __half2(h0, h1);
    hp[i*2+1] = __half2(h2, h3);
    lp[i*2]   = __half2(l0, l1);
    lp[i*2+1] = __half2(l2, l3);
}

// transpose W [1024,512] f32 -> Wt [512,1024] fp16
__global__ __launch_bounds__(256) void prep_w(
    const float* __restrict__ wz, const float* __restrict__ wf, const float* __restrict__ wo)
{
    __shared__ float tile[32][33];
    const int gate = blockIdx.z;
    const float* W = (gate == 0) ? wz : ((gate == 1) ? wf : wo);
    const int kk0 = blockIdx.x * 32, h0 = blockIdx.y * 32;
    const int tx = threadIdx.x & 31, ty = threadIdx.x >> 5;   // 32 x 8
    for (int i = ty; i < 32; i += 8)
        tile[i][tx] = W[(size_t)(kk0 + i) * Hdim + h0 + tx];
    __syncthreads();
    for (int i = ty; i < 32; i += 8) {
        float v = tile[tx][i];                                 // W[kk0+tx][h0+i]
        g_wt[gate][(size_t)(h0 + i) * 1024 + kk0 + tx] = __float2half(v);
    }
}

// ---------------- HMMA GEMM ----------------
// grid (N/BN=4, M/BM=256, 3 gates), 256 threads (8 warps as 4m x 2n)
__global__ __launch_bounds__(256, 2) void gate_gemm_mma(
    const float* __restrict__ bz, const float* __restrict__ bf_,
    const float* __restrict__ bo)
{
    extern __shared__ char smem[];
    const uint32_t sb = smem_u32(smem);
    const int tid = threadIdx.x, lane = tid & 31, wid = tid >> 5;
    const int wm = wid & 3, wn = wid >> 2;
    const int gate = blockIdx.z;
    const int n0 = blockIdx.x * BN;
    const int m0 = blockIdx.y * BM;

    const float* bias = (gate == 0) ? bz : ((gate == 1) ? bf_ : bo);
    float* outg       = (gate == 0) ? g_z : ((gate == 1) ? g_f : g_o);
    const __half* wt = g_wt[gate];

    const int arow = tid >> 2;        // 0..63 (two rows: arow, arow+64)
    const int aseg = tid & 3;         // 16B segment within 64B row

    auto load_stage = [&](int it) {
        const int term = it >> 5;                 // 0: hi(A), 1: lo(A)
        const int kidx = (it & 31) * 32;          // 0..992
        const __half* Ap = term ? g_xlo : g_xhi;
        const int shift = (kidx < 512) ? 1 : 0;   // tap t-1 vs t
        const int acolB = ((kidx & 511) * 2) + aseg * 16;
        const int wcolB = kidx * 2 + aseg * 16;
        const uint32_t as = sb + (it & (STAGES - 1)) * STG;
        const uint32_t bs = as + ASTG;
        #pragma unroll
        for (int h = 0; h < 2; h++) {
            const int r = arow + h * 64;
            const int m = m0 + r;
            const char* src = (const char*)Ap + (size_t)(m - shift) * 1024 + acolB;
            uint32_t sz = 16;
            if (shift && ((m & (Tlen - 1)) == 0)) { sz = 0; src = (const char*)Ap; }
            cpa16(as + r * AROWB + aseg * 16, src, sz);
        }
        #pragma unroll
        for (int h = 0; h < 2; h++) {
            const int r = arow + h * 64;
            const char* src = (const char*)wt + (size_t)(n0 + r) * 2048 + wcolB;
            cpa16(bs + r * AROWB + aseg * 16, src, 16);
        }
    };

    load_stage(0); CP_COMMIT();
    load_stage(1); CP_COMMIT();
    load_stage(2); CP_COMMIT();

    float acc[2][8][4];
    #pragma unroll
    for (int f = 0; f < 2; f++)
        #pragma unroll
        for (int n = 0; n < 8; n++)
            #pragma unroll
            for (int q = 0; q < 4; q++) acc[f][n][q] = 0.0f;

    // per-lane ldmatrix base offsets
    const uint32_t aBase = (uint32_t)((wm * 32 + (lane & 15)) * AROWB + (lane >> 4) * 16);
    const uint32_t bBase = (uint32_t)((wn * 64 + (lane & 15)) * AROWB + (lane >> 4) * 16);

    uint32_t afA[2][4], afB[2][4], bg[4][4];

    // prologue: stage 0 ready for all threads, preload (it=0, jk0) A-frags
    CP_WAIT2();
    __syncthreads();
    {
        const uint32_t as = sb;
        LDSM4(afA[0], as + aBase);
        LDSM4(afA[1], as + aBase + 16 * AROWB);
    }

    for (int it = 0; it < NIT; it++) {
        // top barrier: all warps finished reading slot (it-1)&3 -> safe to overwrite
        __syncthreads();
        if (it + 3 < NIT) load_stage(it + 3);
        CP_COMMIT();

        const uint32_t as = sb + (it & (STAGES - 1)) * STG;
        const uint32_t bs = as + ASTG;

        // jk0 B-frags + jk1 A-frags (stage it, already visible)
        #pragma unroll
        for (int g = 0; g < 4; g++)
            LDSM4(bg[g], bs + bBase + g * 16 * AROWB);
        LDSM4(afB[0], as + aBase + 32);
        LDSM4(afB[1], as + aBase + 16 * AROWB + 32);

        // MMA jk0
        #pragma unroll
        for (int f = 0; f < 2; f++)
            #pragma unroll
            for (int nt = 0; nt < 8; nt++) {
                const int g = nt >> 1, p = nt & 1;
                mma16816(acc[f][nt], afA[f], bg[g][p], bg[g][p + 2]);
            }

        // jk1 B-frags (reuse bg registers)
        #pragma unroll
        for (int g = 0; g < 4; g++)
            LDSM4(bg[g], bs + bBase + g * 16 * AROWB + 32);

        // make stage it+1 visible and prefetch its jk0 A-frags
        if (it + 1 < NIT) {
            CP_WAIT2();
            __syncthreads();
            const uint32_t as2 = sb + ((it + 1) & (STAGES - 1)) * STG;
            LDSM4(afA[0], as2 + aBase);
            LDSM4(afA[1], as2 + aBase + 16 * AROWB);
        }

        // MMA jk1
        #pragma unroll
        for (int f = 0; f < 2; f++)
            #pragma unroll
            for (int nt = 0; nt < 8; nt++) {
                const int g = nt >> 1, p = nt & 1;
                mma16816(acc[f][nt], afB[f], bg[g][p], bg[g][p + 2]);
            }
    }

    // epilogue: bias + activation + direct stores
    #pragma unroll
    for (int f = 0; f < 2; f++) {
        const int rbase = m0 + wm * 32 + f * 16 + (lane >> 2);
        #pragma unroll
        for (int nt = 0; nt < 8; nt++) {
            const int col = n0 + wn * 64 + nt * 8 + (lane & 3) * 2;
            const float b0 = __ldg(bias + col), b1 = __ldg(bias + col + 1);
            float v0 = acc[f][nt][0] + b0, v1 = acc[f][nt][1] + b1;
            float v2 = acc[f][nt][2] + b0, v3 = acc[f][nt][3] + b1;
            if (gate == 0) {
                v0 = tanhf(v0); v1 = tanhf(v1); v2 = tanhf(v2); v3 = tanhf(v3);
            } else {
                v0 = 1.0f / (1.0f + __expf(-v0));
                v1 = 1.0f / (1.0f + __expf(-v1));
                v2 = 1.0f / (1.0f + __expf(-v2));
                v3 = 1.0f / (1.0f + __expf(-v3));
            }
            float2 lo = make_float2(v0, v1), hi = make_float2(v2, v3);
            *(float2*)(outg + (size_t)rbase * Hdim + col) = lo;
            *(float2*)(outg + (size_t)(rbase + 8) * Hdim + col) = hi;
        }
    }
}

// ---------------- scan (chunked linear recurrence) ----------------
__global__ __launch_bounds__(Hdim) void chunk_reduce()
{
    const int h = threadIdx.x, c = blockIdx.x, b = blockIdx.y;
    size_t base = (size_t)(b * Tlen + c * CHUNK) * Hdim + h;
    float P = 1.0f, L = 0.0f;
    #pragma unroll 4
    for (int i = 0; i < CHUNK; i++) {
        const size_t idx = base + (size_t)i * Hdim;
        const float f = g_f[idx], z = g_z[idx];
        L = fmaf(f, L, (1.0f - f) * z);
        P *= f;
    }
    const size_t ci = (size_t)(b * NCH + c) * Hdim + h;
    g_P[ci] = P; g_L[ci] = L;
}

__global__ __launch_bounds__(Hdim) void chunk_prefix()
{
    const int h = threadIdx.x, b = blockIdx.x;
    float hc = 0.0f;
    for (int c = 0; c < NCH; c++) {
        const size_t idx = (size_t)(b * NCH + c) * Hdim + h;
        g_hin[idx] = hc;
        hc = fmaf(g_P[idx], hc, g_L[idx]);
    }
}

__global__ __launch_bounds__(Hdim) void chunk_apply(float* __restrict__ out)
{
    const int h = threadIdx.x, c = blockIdx.x, b = blockIdx.y;
    float hc = g_hin[(size_t)(b * NCH + c) * Hdim + h];
    size_t base = (size_t)(b * Tlen + c * CHUNK) * Hdim + h;
    #pragma unroll 4
    for (int i = 0; i < CHUNK; i++) {
        const size_t idx = base + (size_t)i * Hdim;
        const float f = g_f[idx], z = g_z[idx], o = g_o[idx];
        hc = fmaf(f, hc, (1.0f - f) * z);
        out[idx] = hc * o;
    }
}

// ---------------- launch ----------------
extern "C" void kernel_launch(void* const* d_in, const int* in_sizes, int n_in,
                              void* d_out, int out_size)
{
    const float* x  = (const float*)d_in[0];
    const float* wz = (const float*)d_in[1];
    const float* bz = (const float*)d_in[2];
    const float* wf = (const float*)d_in[3];
    const float* bf = (const float*)d_in[4];
    const float* wo = (const float*)d_in[5];
    const float* bo = (const float*)d_in[6];
    float* out = (float*)d_out;

    cudaFuncSetAttribute(gate_gemm_mma, cudaFuncAttributeMaxDynamicSharedMemorySize, SMEMT);

    prep_x<<<(size_t)Mtot * Cdim / 4 / 256, 256>>>(x);
    prep_w<<<dim3(1024 / 32, Hdim / 32, 3), 256>>>(wz, wf, wo);

    gate_gemm_mma<<<dim3(Hdim / BN, Mtot / BM, 3), 256, SMEMT>>>(bz, bf, bo);

    chunk_reduce<<<dim3(NCH, Bsz), Hdim>>>();
    chunk_prefix<<<Bsz, Hdim>>>();
    chunk_apply<<<dim3(NCH, Bsz), Hdim>>>(out);
}

// round 7
// speedup vs baseline: 1.7046x; 1.7046x over previous
#include <cuda_runtime.h>
#include <cuda_fp16.h>
#include <stdint.h>
#include <math.h>

// ---------------- problem constants ----------------
#define Bsz   8
#define Tlen  4096
#define Cdim  512
#define Hdim  512
#define Mtot  (Bsz * Tlen)          // 32768 rows
#define NCH   64
#define CHUNK (Tlen / NCH)          // 64

// ---------------- GEMM tiling ----------------
#define BM     128
#define BN     128
#define STAGES 4
#define NIT    32                   // single fp16 term, K=1024
#define AROWB  80                   // padded smem row stride (bytes)
#define ASTG   (BM * AROWB)         // 10240
#define BSTG   (BN * AROWB)         // 10240
#define STG    (ASTG + BSTG)        // 20480
#define SMEMT  (STAGES * STG)       // 81920

// ---------------- device scratch ----------------
__device__ __half g_z[(size_t)Mtot * Hdim];
__device__ __half g_f[(size_t)Mtot * Hdim];
__device__ __half g_o[(size_t)Mtot * Hdim];
__device__ float g_P[Bsz * NCH * Hdim];
__device__ float g_L[Bsz * NCH * Hdim];
__device__ float g_hin[Bsz * NCH * Hdim];
__device__ __half g_xh[(size_t)Mtot * Cdim];
__device__ __half g_wt[3][(size_t)Hdim * 2 * Cdim];   // [gate][h*1024 + kk], fp16

// ---------------- PTX helpers ----------------
__device__ __forceinline__ uint32_t smem_u32(const void* p) {
    uint32_t a;
    asm("{ .reg .u64 t; cvta.to.shared.u64 t, %1; cvt.u32.u64 %0, t; }" : "=r"(a) : "l"(p));
    return a;
}
__device__ __forceinline__ void cpa16(uint32_t dst, const void* src, uint32_t sz) {
    asm volatile("cp.async.cg.shared.global [%0], [%1], 16, %2;"
                 :: "r"(dst), "l"(src), "r"(sz) : "memory");
}
#define CP_COMMIT() asm volatile("cp.async.commit_group;" ::: "memory")
#define CP_WAIT2()  asm volatile("cp.async.wait_group 2;" ::: "memory")

#define LDSM4(r, a) \
    asm volatile("ldmatrix.sync.aligned.m8n8.x4.shared.b16 {%0,%1,%2,%3}, [%4];" \
        : "=r"((r)[0]), "=r"((r)[1]), "=r"((r)[2]), "=r"((r)[3]) : "r"(a))

__device__ __forceinline__ void mma16816(float* c, const uint32_t* a,
                                         uint32_t b0, uint32_t b1) {
    asm volatile(
        "mma.sync.aligned.m16n8k16.row.col.f32.f16.f16.f32 "
        "{%0,%1,%2,%3}, {%4,%5,%6,%7}, {%8,%9}, {%0,%1,%2,%3};"
        : "+f"(c[0]), "+f"(c[1]), "+f"(c[2]), "+f"(c[3])
        : "r"(a[0]), "r"(a[1]), "r"(a[2]), "r"(a[3]), "r"(b0), "r"(b1));
}

// ---------------- prep kernels ----------------
__global__ __launch_bounds__(256) void prep_x(const float* __restrict__ x) {
    size_t i = (size_t)blockIdx.x * 256 + threadIdx.x;   // over Mtot*Cdim/4
    float4 v = ((const float4*)x)[i];
    __half2* hp = (__half2*)g_xh;
    hp[i*2]   = __floats2half2_rn(v.x, v.y);
    hp[i*2+1] = __floats2half2_rn(v.z, v.w);
}

// transpose W [1024,512] f32 -> Wt [512,1024] fp16
__global__ __launch_bounds__(256) void prep_w(
    const float* __restrict__ wz, const float* __restrict__ wf, const float* __restrict__ wo)
{
    __shared__ float tile[32][33];
    const int gate = blockIdx.z;
    const float* W = (gate == 0) ? wz : ((gate == 1) ? wf : wo);
    const int kk0 = blockIdx.x * 32, h0 = blockIdx.y * 32;
    const int tx = threadIdx.x & 31, ty = threadIdx.x >> 5;   // 32 x 8
    for (int i = ty; i < 32; i += 8)
        tile[i][tx] = W[(size_t)(kk0 + i) * Hdim + h0 + tx];
    __syncthreads();
    for (int i = ty; i < 32; i += 8) {
        float v = tile[tx][i];                                 // W[kk0+tx][h0+i]
        g_wt[gate][(size_t)(h0 + i) * 1024 + kk0 + tx] = __float2half(v);
    }
}

// ---------------- HMMA GEMM ----------------
// grid (N/BN=4, M/BM=256, 3 gates), 256 threads (8 warps as 4m x 2n)
__global__ __launch_bounds__(256, 2) void gate_gemm_mma(
    const float* __restrict__ bz, const float* __restrict__ bf_,
    const float* __restrict__ bo)
{
    extern __shared__ char smem[];
    const uint32_t sb = smem_u32(smem);
    const int tid = threadIdx.x, lane = tid & 31, wid = tid >> 5;
    const int wm = wid & 3, wn = wid >> 2;
    const int gate = blockIdx.z;
    const int n0 = blockIdx.x * BN;
    const int m0 = blockIdx.y * BM;

    const float* bias = (gate == 0) ? bz : ((gate == 1) ? bf_ : bo);
    __half* outg      = (gate == 0) ? g_z : ((gate == 1) ? g_f : g_o);
    const __half* wt = g_wt[gate];

    const int arow = tid >> 2;        // 0..63 (two rows: arow, arow+64)
    const int aseg = tid & 3;         // 16B segment within 64B row

    auto load_stage = [&](int it) {
        const int kidx = it * 32;                 // 0..992
        const int shift = (kidx < 512) ? 1 : 0;   // tap t-1 vs t
        const int acolB = ((kidx & 511) * 2) + aseg * 16;
        const int wcolB = kidx * 2 + aseg * 16;
        const uint32_t as = sb + (it & (STAGES - 1)) * STG;
        const uint32_t bs = as + ASTG;
        #pragma unroll
        for (int h = 0; h < 2; h++) {
            const int r = arow + h * 64;
            const int m = m0 + r;
            const char* src = (const char*)g_xh + (size_t)(m - shift) * 1024 + acolB;
            uint32_t sz = 16;
            if (shift && ((m & (Tlen - 1)) == 0)) { sz = 0; src = (const char*)g_xh; }
            cpa16(as + r * AROWB + aseg * 16, src, sz);
        }
        #pragma unroll
        for (int h = 0; h < 2; h++) {
            const int r = arow + h * 64;
            const char* src = (const char*)wt + (size_t)(n0 + r) * 2048 + wcolB;
            cpa16(bs + r * AROWB + aseg * 16, src, 16);
        }
    };

    load_stage(0); CP_COMMIT();
    load_stage(1); CP_COMMIT();
    load_stage(2); CP_COMMIT();

    float acc[2][8][4];
    #pragma unroll
    for (int f = 0; f < 2; f++)
        #pragma unroll
        for (int n = 0; n < 8; n++)
            #pragma unroll
            for (int q = 0; q < 4; q++) acc[f][n][q] = 0.0f;

    // per-lane ldmatrix base offsets
    const uint32_t aBase = (uint32_t)((wm * 32 + (lane & 15)) * AROWB + (lane >> 4) * 16);
    const uint32_t bBase = (uint32_t)((wn * 64 + (lane & 15)) * AROWB + (lane >> 4) * 16);

    for (int it = 0; it < NIT; it++) {
        CP_WAIT2();
        __syncthreads();
        // issue next stage's loads BEFORE compute: slot (it+3)&3 == (it-1)&3,
        // whose reads all completed before the barrier above.
        if (it + 3 < NIT) load_stage(it + 3);
        CP_COMMIT();

        const uint32_t as = sb + (it & (STAGES - 1)) * STG;
        const uint32_t bs = as + ASTG;
        #pragma unroll
        for (int jk = 0; jk < 2; jk++) {
            uint32_t af[2][4], bg[4][4];
            LDSM4(af[0], as + aBase + jk * 32);
            LDSM4(af[1], as + aBase + 16 * AROWB + jk * 32);
            #pragma unroll
            for (int g = 0; g < 4; g++)
                LDSM4(bg[g], bs + bBase + g * 16 * AROWB + jk * 32);
            #pragma unroll
            for (int f = 0; f < 2; f++)
                #pragma unroll
                for (int nt = 0; nt < 8; nt++) {
                    const int g = nt >> 1, p = nt & 1;
                    mma16816(acc[f][nt], af[f], bg[g][p], bg[g][p + 2]);
                }
        }
    }

    // epilogue: bias + activation + fp16 stores
    #pragma unroll
    for (int f = 0; f < 2; f++) {
        const int rbase = m0 + wm * 32 + f * 16 + (lane >> 2);
        #pragma unroll
        for (int nt = 0; nt < 8; nt++) {
            const int col = n0 + wn * 64 + nt * 8 + (lane & 3) * 2;
            const float b0 = __ldg(bias + col), b1 = __ldg(bias + col + 1);
            float v0 = acc[f][nt][0] + b0, v1 = acc[f][nt][1] + b1;
            float v2 = acc[f][nt][2] + b0, v3 = acc[f][nt][3] + b1;
            if (gate == 0) {
                v0 = tanhf(v0); v1 = tanhf(v1); v2 = tanhf(v2); v3 = tanhf(v3);
            } else {
                v0 = 1.0f / (1.0f + __expf(-v0));
                v1 = 1.0f / (1.0f + __expf(-v1));
                v2 = 1.0f / (1.0f + __expf(-v2));
                v3 = 1.0f / (1.0f + __expf(-v3));
            }
            *(__half2*)(outg + (size_t)rbase * Hdim + col)       = __floats2half2_rn(v0, v1);
            *(__half2*)(outg + (size_t)(rbase + 8) * Hdim + col) = __floats2half2_rn(v2, v3);
        }
    }
}

// ---------------- scan (chunked linear recurrence) ----------------
__global__ __launch_bounds__(Hdim) void chunk_reduce()
{
    const int h = threadIdx.x, c = blockIdx.x, b = blockIdx.y;
    size_t base = (size_t)(b * Tlen + c * CHUNK) * Hdim + h;
    float P = 1.0f, L = 0.0f;
    #pragma unroll 4
    for (int i = 0; i < CHUNK; i++) {
        const size_t idx = base + (size_t)i * Hdim;
        const float f = __half2float(g_f[idx]);
        const float z = __half2float(g_z[idx]);
        L = fmaf(f, L, (1.0f - f) * z);
        P *= f;
    }
    const size_t ci = (size_t)(b * NCH + c) * Hdim + h;
    g_P[ci] = P; g_L[ci] = L;
}

__global__ __launch_bounds__(Hdim) void chunk_prefix()
{
    const int h = threadIdx.x, b = blockIdx.x;
    float hc = 0.0f;
    for (int c = 0; c < NCH; c++) {
        const size_t idx = (size_t)(b * NCH + c) * Hdim + h;
        g_hin[idx] = hc;
        hc = fmaf(g_P[idx], hc, g_L[idx]);
    }
}

__global__ __launch_bounds__(Hdim) void chunk_apply(float* __restrict__ out)
{
    const int h = threadIdx.x, c = blockIdx.x, b = blockIdx.y;
    float hc = g_hin[(size_t)(b * NCH + c) * Hdim + h];
    size_t base = (size_t)(b * Tlen + c * CHUNK) * Hdim + h;
    #pragma unroll 4
    for (int i = 0; i < CHUNK; i++) {
        const size_t idx = base + (size_t)i * Hdim;
        const float f = __half2float(g_f[idx]);
        const float z = __half2float(g_z[idx]);
        const float o = __half2float(g_o[idx]);
        hc = fmaf(f, hc, (1.0f - f) * z);
        out[idx] = hc * o;
    }
}

// ---------------- launch ----------------
extern "C" void kernel_launch(void* const* d_in, const int* in_sizes, int n_in,
                              void* d_out, int out_size)
{
    const float* x  = (const float*)d_in[0];
    const float* wz = (const float*)d_in[1];
    const float* bz = (const float*)d_in[2];
    const float* wf = (const float*)d_in[3];
    const float* bf = (const float*)d_in[4];
    const float* wo = (const float*)d_in[5];
    const float* bo = (const float*)d_in[6];
    float* out = (float*)d_out;

    cudaFuncSetAttribute(gate_gemm_mma, cudaFuncAttributeMaxDynamicSharedMemorySize, SMEMT);

    prep_x<<<(size_t)Mtot * Cdim / 4 / 256, 256>>>(x);
    prep_w<<<dim3(1024 / 32, Hdim / 32, 3), 256>>>(wz, wf, wo);

    gate_gemm_mma<<<dim3(Hdim / BN, Mtot / BM, 3), 256, SMEMT>>>(bz, bf, bo);

    chunk_reduce<<<dim3(NCH, Bsz), Hdim>>>();
    chunk_prefix<<<Bsz, Hdim>>>();
    chunk_apply<<<dim3(NCH, Bsz), Hdim>>>(out);
}